// round 7
// baseline (speedup 1.0000x reference)
#include <cuda_runtime.h>
#include <cuda_fp16.h>

#define D 128
#define N_MAX 100000
#define E_MAX 640000
#define RSH 5                 // 32 rows per bucket
#define NB_PAD 4096           // scan capacity (4 per thread x 1024)
#define SC_CHUNK 16384        // edges per scatter block

// Normalized rows in fp16: 25.6 MB (L2-resident).
__device__ __half g_xh[N_MAX * D];
// Sort scratch.
__device__ int g_cnt[NB_PAD];
__device__ int g_off[NB_PAD + 1];
__device__ int g_cur[NB_PAD];
__device__ int g_sidx[E_MAX];
__device__ int g_didx[E_MAX];
__device__ int g_eid[E_MAX];

// ---------------- sort chain ----------------

__global__ void zero_kernel() {
    int i = blockIdx.x * blockDim.x + threadIdx.x;
    if (i < NB_PAD) g_cnt[i] = 0;
}

__global__ void hist_kernel(const int* __restrict__ src, int e, int n) {
    for (int i = blockIdx.x * blockDim.x + threadIdx.x; i < e;
         i += gridDim.x * blockDim.x) {
        int s = __ldg(src + i);
        if ((unsigned)s < (unsigned)n) atomicAdd(&g_cnt[s >> RSH], 1);
    }
}

// Single block, 1024 threads, 4 elements per thread -> exclusive scan of 4096.
__global__ void scan_kernel() {
    __shared__ int sh[1024];
    int t = threadIdx.x;
    int a0 = g_cnt[4 * t + 0];
    int a1 = g_cnt[4 * t + 1];
    int a2 = g_cnt[4 * t + 2];
    int a3 = g_cnt[4 * t + 3];
    int sum = a0 + a1 + a2 + a3;
    sh[t] = sum;
    __syncthreads();
    // Hillis-Steele inclusive scan over 1024 group sums.
    for (int o = 1; o < 1024; o <<= 1) {
        int add = (t >= o) ? sh[t - o] : 0;
        __syncthreads();
        sh[t] += add;
        __syncthreads();
    }
    int excl = sh[t] - sum;   // exclusive prefix of this 4-group
    int v0 = excl;
    int v1 = excl + a0;
    int v2 = v1 + a1;
    int v3 = v2 + a2;
    g_off[4 * t + 0] = v0;  g_cur[4 * t + 0] = v0;
    g_off[4 * t + 1] = v1;  g_cur[4 * t + 1] = v1;
    g_off[4 * t + 2] = v2;  g_cur[4 * t + 2] = v2;
    g_off[4 * t + 3] = v3;  g_cur[4 * t + 3] = v3;
    if (t == 1023) g_off[4096] = sh[1023] - sum + sum;  // = total
}

// Aggregated scatter: each block claims per-bucket contiguous runs, so the
// (sidx, didx, eid) writes are mostly sector-contiguous.
__global__ void scatter_kernel(const int* __restrict__ src,
                               const int* __restrict__ dst,
                               int e, int n, int nb) {
    __shared__ int h[3200];
    __shared__ int base[3200];
    __shared__ int curs[3200];
    int tid = threadIdx.x;
    int c0 = blockIdx.x * SC_CHUNK;
    int c1 = min(c0 + SC_CHUNK, e);

    for (int b = tid; b < nb; b += blockDim.x) { h[b] = 0; curs[b] = 0; }
    __syncthreads();
    for (int i = c0 + tid; i < c1; i += blockDim.x) {
        int s = __ldg(src + i);
        if ((unsigned)s < (unsigned)n) atomicAdd(&h[s >> RSH], 1);
    }
    __syncthreads();
    for (int b = tid; b < nb; b += blockDim.x) {
        int c = h[b];
        base[b] = c ? atomicAdd(&g_cur[b], c) : 0;
    }
    __syncthreads();
    for (int i = c0 + tid; i < c1; i += blockDim.x) {
        int s = __ldg(src + i);
        if ((unsigned)s >= (unsigned)n) continue;
        int b = s >> RSH;
        int r = atomicAdd(&curs[b], 1);
        int p = base[b] + r;
        g_sidx[p] = s;
        g_didx[p] = __ldg(dst + i);
        g_eid[p]  = i;
    }
}

// ---------------- compute kernels ----------------

// One warp per row. fp32 norm, write fp16 row.
__global__ void normalize_kernel(const float* __restrict__ x, int n) {
    int warp = (blockIdx.x * blockDim.x + threadIdx.x) >> 5;
    int lane = threadIdx.x & 31;
    if (warp >= n) return;
    const float4* row = reinterpret_cast<const float4*>(x + (size_t)warp * D);
    float4 v = __ldg(row + lane);
    float ss = v.x * v.x + v.y * v.y + v.z * v.z + v.w * v.w;
#pragma unroll
    for (int o = 16; o; o >>= 1) ss += __shfl_xor_sync(0xffffffffu, ss, o);
    float r = 1.0f / fmaxf(sqrtf(ss), 1e-12f);
    __half2 h0 = __floats2half2_rn(v.x * r, v.y * r);
    __half2 h1 = __floats2half2_rn(v.z * r, v.w * r);
    uint2 packed;
    packed.x = *reinterpret_cast<unsigned*>(&h0);
    packed.y = *reinterpret_cast<unsigned*>(&h1);
    reinterpret_cast<uint2*>(g_xh + (size_t)warp * D)[lane] = packed;
}

// One block per bucket. Edges in [g_off[b], g_off[b+1]) have src confined to
// a 32-row (8 KB) window -> src gathers are L1-hot after first touch.
// dst gathers stream via __ldcs. 8 edges per warp per iteration, same
// LDG.128 two-rows-per-instruction + value-packing butterfly as before.
__global__ void __launch_bounds__(256, 4)
edge_dot_kernel(float* __restrict__ out, int e, int n) {
    int b = blockIdx.x;
    int start = __ldg(&g_off[b]);
    int end   = __ldg(&g_off[b + 1]);
    int warpId = threadIdx.x >> 5;
    int lane = threadIdx.x & 31;

    const int laneHi = lane >> 4;    // 0: even edges, 1: odd edges
    const int lane15 = lane & 15;
    const char* basep = reinterpret_cast<const char*>(g_xh);
    const unsigned laneOff = (unsigned)lane15 * 16u;

    for (int k0 = start + warpId * 8; k0 < end; k0 += 8 * 8) {
        // lanes 0..7 -> sidx[k0+lane], lanes 8..15 -> didx[k0+lane-8]
        int myidx = 0;
        if (lane < 16) {
            int k = k0 + (lane & 7);
            if (k < end) {
                myidx = (lane < 8) ? __ldg(&g_sidx[k]) : __ldg(&g_didx[k]);
                if ((unsigned)myidx >= (unsigned)n) myidx = 0;  // defensive
            }
        }

        int rs[4], rd[4];
#pragma unroll
        for (int k = 0; k < 4; k++) {
            rs[k] = __shfl_sync(0xffffffffu, myidx, 2 * k + laneHi);
            rd[k] = __shfl_sync(0xffffffffu, myidx, 8 + 2 * k + laneHi);
        }

        uint4 a[4], bb[4];
#pragma unroll
        for (int k = 0; k < 4; k++)
            a[k] = __ldg(reinterpret_cast<const uint4*>(
                basep + ((unsigned)rs[k] * 256u + laneOff)));
#pragma unroll
        for (int k = 0; k < 4; k++)
            bb[k] = __ldcs(reinterpret_cast<const uint4*>(
                basep + ((unsigned)rd[k] * 256u + laneOff)));

        float acc[4];
#pragma unroll
        for (int k = 0; k < 4; k++) {
            __half2 a0 = *reinterpret_cast<__half2*>(&a[k].x);
            __half2 a1 = *reinterpret_cast<__half2*>(&a[k].y);
            __half2 a2 = *reinterpret_cast<__half2*>(&a[k].z);
            __half2 a3 = *reinterpret_cast<__half2*>(&a[k].w);
            __half2 b0 = *reinterpret_cast<__half2*>(&bb[k].x);
            __half2 b1 = *reinterpret_cast<__half2*>(&bb[k].y);
            __half2 b2 = *reinterpret_cast<__half2*>(&bb[k].z);
            __half2 b3 = *reinterpret_cast<__half2*>(&bb[k].w);
            __half2 g0 = __hfma2(a1, b1, __hmul2(a0, b0));
            __half2 g1 = __hfma2(a3, b3, __hmul2(a2, b2));
            float2 f0 = __half22float2(g0);
            float2 f1 = __half22float2(g1);
            acc[k] = (f0.x + f0.y) + (f1.x + f1.y);
        }

        // Value-packing butterfly within 16-lane halves.
#pragma unroll
        for (int k = 0; k < 4; k++)
            acc[k] += __shfl_xor_sync(0xffffffffu, acc[k], 8);
        float m0 = (lane & 8) ? acc[1] : acc[0];
        float m1 = (lane & 8) ? acc[3] : acc[2];
        m0 += __shfl_xor_sync(0xffffffffu, m0, 4);
        m1 += __shfl_xor_sync(0xffffffffu, m1, 4);
        float q = (lane & 4) ? m1 : m0;
        q += __shfl_xor_sync(0xffffffffu, q, 2);
        q += __shfl_xor_sync(0xffffffffu, q, 1);

        if ((lane & 3) == 0) {
            int k = ((lane >> 3) & 1) + ((lane & 4) ? 2 : 0);
            int pos = k0 + 2 * k + laneHi;
            if (pos < end) out[__ldg(&g_eid[pos])] = q;
        }
    }
}

extern "C" void kernel_launch(void* const* d_in, const int* in_sizes, int n_in,
                              void* d_out, int out_size) {
    const float* x   = (const float*)d_in[0];
    const int*   src = (const int*)d_in[1];
    const int*   dst = (const int*)d_in[2];
    float*       out = (float*)d_out;

    int n = in_sizes[0] / D;   // 100000
    int e = in_sizes[1];       // 640000
    int nb = (n + 31) >> RSH;  // 3125 buckets (<= 3200 smem arrays, <= 4096 scan)

    // Sort chain (independent of x).
    zero_kernel<<<(NB_PAD + 1023) / 1024, 1024>>>();
    hist_kernel<<<256, 256>>>(src, e, n);
    scan_kernel<<<1, 1024>>>();
    int sblk = (e + SC_CHUNK - 1) / SC_CHUNK;
    scatter_kernel<<<sblk, 256>>>(src, dst, e, n, nb);

    // Normalize.
    int nblk1 = (n + 7) / 8;   // 8 warps/block
    normalize_kernel<<<nblk1, 256>>>(x, n);

    // Edge scoring: one block per bucket.
    edge_dot_kernel<<<nb, 256>>>(out, e, n);
}

// round 8
// speedup vs baseline: 3.5760x; 3.5760x over previous
#include <cuda_runtime.h>
#include <cuda_fp16.h>

#define N_MAX 100000
#define D 128
// Normalized rows in fp16: 100000 x 128 x 2B = 25.6 MB (L2-resident).
__device__ __half g_xh[N_MAX * D];

// Kernel 1: one warp per row. fp32 norm, write fp16 row. Streaming read of x
// (evict-first) keeps L2 free for g_xh, which the edge kernel re-reads.
__global__ void normalize_kernel(const float* __restrict__ x, int n) {
    int warp = (blockIdx.x * blockDim.x + threadIdx.x) >> 5;
    int lane = threadIdx.x & 31;
    if (warp >= n) return;
    const float4* row = reinterpret_cast<const float4*>(x + (size_t)warp * D);
    float4 v = __ldcs(row + lane);
    float ss = v.x * v.x + v.y * v.y + v.z * v.z + v.w * v.w;
#pragma unroll
    for (int o = 16; o; o >>= 1) ss += __shfl_xor_sync(0xffffffffu, ss, o);
    float r = 1.0f / fmaxf(sqrtf(ss), 1e-12f);
    __half2 h0 = __floats2half2_rn(v.x * r, v.y * r);
    __half2 h1 = __floats2half2_rn(v.z * r, v.w * r);
    uint2 packed;
    packed.x = *reinterpret_cast<unsigned*>(&h0);
    packed.y = *reinterpret_cast<unsigned*>(&h1);
    reinterpret_cast<uint2*>(g_xh + (size_t)warp * D)[lane] = packed;
}

// Kernel 2: one warp = 8 edges. Each LDG.128 gathers TWO rows (16 lanes x 16B
// per row): 8 gather instructions per warp. half2 math with early fp32
// conversion; value-packing butterfly reduces all 8 edges in 8 SHFL total;
// 8 result lanes store one 32B sector.
__global__ void __launch_bounds__(256, 6)
edge_dot_kernel(const int* __restrict__ src,
                const int* __restrict__ dst,
                float* __restrict__ out, int e, int n) {
    int warp = (blockIdx.x * blockDim.x + threadIdx.x) >> 5;
    int lane = threadIdx.x & 31;
    int e0 = warp * 8;
    if (e0 >= e) return;

    // lanes 0..7 -> src[e0+lane], lanes 8..15 -> dst[e0+lane-8]
    int myidx = 0;
    if (lane < 16) {
        int k = e0 + (lane & 7);
        if (k < e) {
            myidx = (lane < 8) ? __ldg(src + k) : __ldg(dst + k);
            if ((unsigned)myidx >= (unsigned)n) myidx = 0;  // defensive
        }
    }

    const int laneHi = lane >> 4;    // 0: even edges, 1: odd edges
    const int lane15 = lane & 15;
    const char* base = reinterpret_cast<const char*>(g_xh);
    const unsigned laneOff = (unsigned)lane15 * 16u;

    int rs[4], rd[4];
#pragma unroll
    for (int k = 0; k < 4; k++) {
        rs[k] = __shfl_sync(0xffffffffu, myidx, 2 * k + laneHi);
        rd[k] = __shfl_sync(0xffffffffu, myidx, 8 + 2 * k + laneHi);
    }

    uint4 a[4], b[4];
#pragma unroll
    for (int k = 0; k < 4; k++)
        a[k] = __ldg(reinterpret_cast<const uint4*>(
            base + ((unsigned)rs[k] * 256u + laneOff)));
#pragma unroll
    for (int k = 0; k < 4; k++)
        b[k] = __ldg(reinterpret_cast<const uint4*>(
            base + ((unsigned)rd[k] * 256u + laneOff)));

    float acc[4];
#pragma unroll
    for (int k = 0; k < 4; k++) {
        __half2 a0 = *reinterpret_cast<__half2*>(&a[k].x);
        __half2 a1 = *reinterpret_cast<__half2*>(&a[k].y);
        __half2 a2 = *reinterpret_cast<__half2*>(&a[k].z);
        __half2 a3 = *reinterpret_cast<__half2*>(&a[k].w);
        __half2 b0 = *reinterpret_cast<__half2*>(&b[k].x);
        __half2 b1 = *reinterpret_cast<__half2*>(&b[k].y);
        __half2 b2 = *reinterpret_cast<__half2*>(&b[k].z);
        __half2 b3 = *reinterpret_cast<__half2*>(&b[k].w);
        __half2 g0 = __hfma2(a1, b1, __hmul2(a0, b0));
        __half2 g1 = __hfma2(a3, b3, __hmul2(a2, b2));
        float2 f0 = __half22float2(g0);
        float2 f1 = __half22float2(g1);
        acc[k] = (f0.x + f0.y) + (f1.x + f1.y);
    }

    // Value-packing butterfly within 16-lane halves.
#pragma unroll
    for (int k = 0; k < 4; k++)
        acc[k] += __shfl_xor_sync(0xffffffffu, acc[k], 8);
    float m0 = (lane & 8) ? acc[1] : acc[0];
    float m1 = (lane & 8) ? acc[3] : acc[2];
    m0 += __shfl_xor_sync(0xffffffffu, m0, 4);
    m1 += __shfl_xor_sync(0xffffffffu, m1, 4);
    float q = (lane & 4) ? m1 : m0;
    q += __shfl_xor_sync(0xffffffffu, q, 2);
    q += __shfl_xor_sync(0xffffffffu, q, 1);

    if ((lane & 3) == 0) {
        int k = ((lane >> 3) & 1) + ((lane & 4) ? 2 : 0);
        int eidx = e0 + 2 * k + laneHi;
        if (eidx < e) out[eidx] = q;
    }
}

extern "C" void kernel_launch(void* const* d_in, const int* in_sizes, int n_in,
                              void* d_out, int out_size) {
    const float* x   = (const float*)d_in[0];
    const int*   src = (const int*)d_in[1];
    const int*   dst = (const int*)d_in[2];
    float*       out = (float*)d_out;

    int n = in_sizes[0] / D;   // 100000
    int e = in_sizes[1];       // 640000

    int nblk1 = (n + 7) / 8;                 // 8 warps/block
    normalize_kernel<<<nblk1, 256>>>(x, n);

    int warps = (e + 7) / 8;
    int nblk2 = (warps + 7) / 8;
    edge_dot_kernel<<<nblk2, 256>>>(src, dst, out, e, n);
}